// round 3
// baseline (speedup 1.0000x reference)
#include <cuda_runtime.h>
#include <cuda_bf16.h>
#include <cstdint>

#define N_NODES 50000
#define N_EDGES 800000
#define NODE_IN 128
#define EDGE_IN 16
#define HIDDEN  128
#define OUT_DIM 128
#define KDIM    (NODE_IN + EDGE_IN)   // 144

// ---------------- scratch (device globals; no allocation allowed) ----------------
__device__ __align__(16) float g_A[(size_t)N_NODES * KDIM];   // [aggX | aggE], stride 144
__device__ __align__(16) float g_h[(size_t)N_NODES * HIDDEN]; // relu(layer1)
__device__ int g_count[N_NODES];
__device__ int g_rowstart[N_NODES];
__device__ int g_cursor[N_NODES];
__device__ int g_perm[N_EDGES];   // edge id, sorted by dst
__device__ int g_src[N_EDGES];    // src node id, sorted by dst
__device__ int g_blocksums[128];
__device__ int g_blockoff[128];
__device__ int g_is64;

// ---------------- index dtype detection ----------------
// int64 indices in [0,50000) => every odd 32-bit word is 0. For int32 the odd
// words are random node ids; probability all 4096 sampled words are zero ~ 0.
__global__ void k_detect(const int* __restrict__ ei) {
    __shared__ int found;
    if (threadIdx.x == 0) found = 0;
    __syncthreads();
    for (int k = threadIdx.x; k < 4096; k += blockDim.x) {
        if (ei[2 * k + 1] != 0) atomicOr(&found, 1);
    }
    __syncthreads();
    if (threadIdx.x == 0) g_is64 = found ? 0 : 1;
}

__device__ __forceinline__ int load_idx(const int* ei, size_t elem, int is64) {
    return is64 ? ei[2 * elem] : ei[elem];
}

// ---------------- CSR build ----------------
__global__ void k_zero_counts() {
    int i = blockIdx.x * blockDim.x + threadIdx.x;
    if (i < N_NODES) g_count[i] = 0;
}

__global__ void k_hist(const int* __restrict__ ei) {
    int e = blockIdx.x * blockDim.x + threadIdx.x;
    if (e >= N_EDGES) return;
    int is64 = g_is64;
    int d = load_idx(ei, (size_t)N_EDGES + e, is64);
    atomicAdd(&g_count[d], 1);
}

// block-local exclusive scan over 512 counts; write block total
__global__ void k_scan1() {
    __shared__ int s[512];
    int t = threadIdx.x;
    int i = blockIdx.x * 512 + t;
    int v = (i < N_NODES) ? g_count[i] : 0;
    s[t] = v;
    __syncthreads();
    for (int off = 1; off < 512; off <<= 1) {
        int tmp = (t >= off) ? s[t - off] : 0;
        __syncthreads();
        s[t] += tmp;
        __syncthreads();
    }
    if (i < N_NODES) g_rowstart[i] = s[t] - v;   // exclusive
    if (t == 511) g_blocksums[blockIdx.x] = s[511];
}

__global__ void k_scan2(int nblocks) {
    __shared__ int s[128];
    int t = threadIdx.x;
    int v = (t < nblocks) ? g_blocksums[t] : 0;
    s[t] = v;
    __syncthreads();
    for (int off = 1; off < 128; off <<= 1) {
        int tmp = (t >= off) ? s[t - off] : 0;
        __syncthreads();
        s[t] += tmp;
        __syncthreads();
    }
    if (t < nblocks) g_blockoff[t] = s[t] - v;   // exclusive
}

__global__ void k_scan3() {
    int i = blockIdx.x * 512 + threadIdx.x;
    if (i < N_NODES) {
        int r = g_rowstart[i] + g_blockoff[blockIdx.x];
        g_rowstart[i] = r;
        g_cursor[i] = r;
    }
}

__global__ void k_scatter(const int* __restrict__ ei) {
    int e = blockIdx.x * blockDim.x + threadIdx.x;
    if (e >= N_EDGES) return;
    int is64 = g_is64;
    int d = load_idx(ei, (size_t)N_EDGES + e, is64);
    int s = load_idx(ei, (size_t)e, is64);
    int pos = atomicAdd(&g_cursor[d], 1);
    g_perm[pos] = e;
    g_src[pos] = s;
}

// ---------------- aggregation: warp per node ----------------
// Sums src-node features (128 f32 = one float4 per lane) into g_A[:, 0:128].
// If WITH_EA, lanes 0..15 also sum edge_attr (16 f32) into g_A[:, 128:144].
template <bool WITH_EA>
__global__ __launch_bounds__(256) void k_agg(const float* __restrict__ feat,
                                             const float* __restrict__ ea) {
    int warp = (blockIdx.x * blockDim.x + threadIdx.x) >> 5;
    int lane = threadIdx.x & 31;
    if (warp >= N_NODES) return;

    int start = g_rowstart[warp];
    int cnt = g_count[warp];
    const float4* xf = (const float4*)feat;

    float4 acc = make_float4(0.f, 0.f, 0.f, 0.f);
    float eacc = 0.f;
    bool do_ea = WITH_EA && (lane < 16);

    // software pipeline: prefetch next src/edge while consuming current
    int s = 0, e = 0;
    if (cnt > 0) {
        s = g_src[start];
        if (WITH_EA) e = g_perm[start];
    }
    for (int i = 0; i < cnt; i++) {
        int s2 = 0, e2 = 0;
        if (i + 1 < cnt) {
            s2 = g_src[start + i + 1];
            if (WITH_EA) e2 = g_perm[start + i + 1];
        }
        float4 v = xf[(size_t)s * 32 + lane];
        acc.x += v.x; acc.y += v.y; acc.z += v.z; acc.w += v.w;
        if (do_ea) eacc += ea[(size_t)e * EDGE_IN + lane];
        s = s2; e = e2;
    }

    ((float4*)(g_A + (size_t)warp * KDIM))[lane] = acc;
    if (do_ea) g_A[(size_t)warp * KDIM + NODE_IN + lane] = eacc;
}

// ---------------- GEMM: C[M,128] = A[M,144] @ W[144,128] + b (opt relu) --------
// BM=128, BN=128, BK=16, 256 threads, 8x8 per thread.
__global__ __launch_bounds__(256) void k_gemm(const float* __restrict__ A, int lda,
                                              const float* __restrict__ W,
                                              const float* __restrict__ bias,
                                              float* __restrict__ C,
                                              int M, int relu) {
    __shared__ float As[16][128];
    __shared__ float Ws[16][128];

    int tid = threadIdx.x;
    int m0 = blockIdx.x * 128;
    int ty = tid >> 4;        // 0..15
    int tx = tid & 15;        // 0..15

    int arow = tid >> 1;          // 0..127
    int acol = (tid & 1) * 8;     // 0 or 8
    int wrow = tid >> 4;          // 0..15
    int wcol = (tid & 15) * 8;    // 0..120

    float acc[8][8];
#pragma unroll
    for (int i = 0; i < 8; i++)
#pragma unroll
        for (int j = 0; j < 8; j++) acc[i][j] = 0.f;

    for (int k0 = 0; k0 < KDIM; k0 += 16) {
        float4 av0 = make_float4(0, 0, 0, 0), av1 = make_float4(0, 0, 0, 0);
        int gr = m0 + arow;
        if (gr < M) {
            const float4* p = (const float4*)(A + (size_t)gr * lda + k0 + acol);
            av0 = p[0];
            av1 = p[1];
        }
        As[acol + 0][arow] = av0.x; As[acol + 1][arow] = av0.y;
        As[acol + 2][arow] = av0.z; As[acol + 3][arow] = av0.w;
        As[acol + 4][arow] = av1.x; As[acol + 5][arow] = av1.y;
        As[acol + 6][arow] = av1.z; As[acol + 7][arow] = av1.w;

        const float4* wp = (const float4*)(W + (size_t)(k0 + wrow) * 128 + wcol);
        float4 w0 = wp[0], w1 = wp[1];
        *(float4*)&Ws[wrow][wcol] = w0;
        *(float4*)&Ws[wrow][wcol + 4] = w1;

        __syncthreads();

#pragma unroll
        for (int k = 0; k < 16; k++) {
            float a[8], b[8];
            *(float4*)(a + 0) = *(const float4*)&As[k][ty * 8];
            *(float4*)(a + 4) = *(const float4*)&As[k][ty * 8 + 4];
            *(float4*)(b + 0) = *(const float4*)&Ws[k][tx * 8];
            *(float4*)(b + 4) = *(const float4*)&Ws[k][tx * 8 + 4];
#pragma unroll
            for (int i = 0; i < 8; i++)
#pragma unroll
                for (int j = 0; j < 8; j++) acc[i][j] += a[i] * b[j];
        }
        __syncthreads();
    }

    float bb[8];
#pragma unroll
    for (int j = 0; j < 8; j++) bb[j] = bias[tx * 8 + j];

#pragma unroll
    for (int i = 0; i < 8; i++) {
        int gr = m0 + ty * 8 + i;
        if (gr < M) {
            float4 o0, o1;
            o0.x = acc[i][0] + bb[0]; o0.y = acc[i][1] + bb[1];
            o0.z = acc[i][2] + bb[2]; o0.w = acc[i][3] + bb[3];
            o1.x = acc[i][4] + bb[4]; o1.y = acc[i][5] + bb[5];
            o1.z = acc[i][6] + bb[6]; o1.w = acc[i][7] + bb[7];
            if (relu) {
                o0.x = fmaxf(o0.x, 0.f); o0.y = fmaxf(o0.y, 0.f);
                o0.z = fmaxf(o0.z, 0.f); o0.w = fmaxf(o0.w, 0.f);
                o1.x = fmaxf(o1.x, 0.f); o1.y = fmaxf(o1.y, 0.f);
                o1.z = fmaxf(o1.z, 0.f); o1.w = fmaxf(o1.w, 0.f);
            }
            float4* cp = (float4*)(C + (size_t)gr * 128 + tx * 8);
            cp[0] = o0;
            cp[1] = o1;
        }
    }
}

// ---------------- launch ----------------
extern "C" void kernel_launch(void* const* d_in, const int* in_sizes, int n_in,
                              void* d_out, int out_size) {
    const float* x  = (const float*)d_in[0];
    const int*   ei = (const int*)d_in[1];   // int32 view; dtype detected on device
    const float* ea = (const float*)d_in[2];
    const float* W1 = (const float*)d_in[3];
    const float* b1 = (const float*)d_in[4];
    const float* W2 = (const float*)d_in[5];
    const float* b2 = (const float*)d_in[6];
    float* out = (float*)d_out;

    const int NB_SCAN = (N_NODES + 511) / 512;            // 98
    const int EB = (N_EDGES + 255) / 256;                 // 3125
    const int AGG_B = (N_NODES * 32 + 255) / 256;         // 6250 (warp per node)
    const int GEMM_B = (N_NODES + 127) / 128;             // 391

    void* p;
    cudaGetSymbolAddress(&p, g_A); float* s_A = (float*)p;
    cudaGetSymbolAddress(&p, g_h); float* s_h = (float*)p;

    k_detect<<<1, 256>>>(ei);
    k_zero_counts<<<(N_NODES + 255) / 256, 256>>>();
    k_hist<<<EB, 256>>>(ei);
    k_scan1<<<NB_SCAN, 512>>>();
    k_scan2<<<1, 128>>>(NB_SCAN);
    k_scan3<<<NB_SCAN, 512>>>();
    k_scatter<<<EB, 256>>>(ei);

    // layer 1: aggregate x + edge_attr, then GEMM with relu -> g_h
    k_agg<true><<<AGG_B, 256>>>(x, ea);
    k_gemm<<<GEMM_B, 256>>>(s_A, KDIM, W1, b1, s_h, N_NODES, 1);

    // layer 2: aggregate h into cols 0..127 (edge cols 128..143 preserved)
    k_agg<false><<<AGG_B, 256>>>(s_h, nullptr);
    k_gemm<<<GEMM_B, 256>>>(s_A, KDIM, W2, b2, out, N_NODES, 0);
}

// round 5
// speedup vs baseline: 1.0665x; 1.0665x over previous
#include <cuda_runtime.h>
#include <cuda_bf16.h>
#include <cstdint>

#define N_NODES 50000
#define N_EDGES 800000
#define NODE_IN 128
#define EDGE_IN 16
#define HIDDEN  128
#define OUT_DIM 128
#define KDIM    (NODE_IN + EDGE_IN)   // 144

// ---------------- scratch (device globals; no allocation allowed) ----------------
__device__ __align__(16) float g_A[(size_t)N_NODES * KDIM];   // [aggX | aggE], stride 144
__device__ __align__(16) float g_h[(size_t)N_NODES * HIDDEN]; // relu(layer1)
__device__ int g_count[N_NODES];
__device__ int g_rowstart[N_NODES];
__device__ int g_cursor[N_NODES];
__device__ int g_perm[N_EDGES];   // edge id, sorted by dst
__device__ int g_src[N_EDGES];    // src node id, sorted by dst
__device__ int g_blocksums[128];
__device__ int g_blockoff[128];
__device__ int g_is64;

// ---------------- index dtype detection ----------------
__global__ void k_detect(const int* __restrict__ ei) {
    __shared__ int found;
    if (threadIdx.x == 0) found = 0;
    __syncthreads();
    for (int k = threadIdx.x; k < 4096; k += blockDim.x) {
        if (ei[2 * k + 1] != 0) atomicOr(&found, 1);
    }
    __syncthreads();
    if (threadIdx.x == 0) g_is64 = found ? 0 : 1;
}

__device__ __forceinline__ int load_idx(const int* ei, size_t elem, int is64) {
    return is64 ? ei[2 * elem] : ei[elem];
}

// ---------------- CSR build ----------------
__global__ void k_zero_counts() {
    int i = blockIdx.x * blockDim.x + threadIdx.x;
    if (i < N_NODES) g_count[i] = 0;
}

__global__ void k_hist(const int* __restrict__ ei) {
    int e = blockIdx.x * blockDim.x + threadIdx.x;
    if (e >= N_EDGES) return;
    int is64 = g_is64;
    int d = load_idx(ei, (size_t)N_EDGES + e, is64);
    atomicAdd(&g_count[d], 1);
}

__global__ void k_scan1() {
    __shared__ int s[512];
    int t = threadIdx.x;
    int i = blockIdx.x * 512 + t;
    int v = (i < N_NODES) ? g_count[i] : 0;
    s[t] = v;
    __syncthreads();
    for (int off = 1; off < 512; off <<= 1) {
        int tmp = (t >= off) ? s[t - off] : 0;
        __syncthreads();
        s[t] += tmp;
        __syncthreads();
    }
    if (i < N_NODES) g_rowstart[i] = s[t] - v;
    if (t == 511) g_blocksums[blockIdx.x] = s[511];
}

__global__ void k_scan2(int nblocks) {
    __shared__ int s[128];
    int t = threadIdx.x;
    int v = (t < nblocks) ? g_blocksums[t] : 0;
    s[t] = v;
    __syncthreads();
    for (int off = 1; off < 128; off <<= 1) {
        int tmp = (t >= off) ? s[t - off] : 0;
        __syncthreads();
        s[t] += tmp;
        __syncthreads();
    }
    if (t < nblocks) g_blockoff[t] = s[t] - v;
}

__global__ void k_scan3() {
    int i = blockIdx.x * 512 + threadIdx.x;
    if (i < N_NODES) {
        int r = g_rowstart[i] + g_blockoff[blockIdx.x];
        g_rowstart[i] = r;
        g_cursor[i] = r;
    }
}

__global__ void k_scatter(const int* __restrict__ ei) {
    int e = blockIdx.x * blockDim.x + threadIdx.x;
    if (e >= N_EDGES) return;
    int is64 = g_is64;
    int d = load_idx(ei, (size_t)N_EDGES + e, is64);
    int s = load_idx(ei, (size_t)e, is64);
    int pos = atomicAdd(&g_cursor[d], 1);
    g_perm[pos] = e;
    g_src[pos] = s;
}

// ---------------- aggregation: warp per node ----------------
template <bool WITH_EA>
__global__ __launch_bounds__(256) void k_agg(const float* __restrict__ feat,
                                             const float* __restrict__ ea) {
    int warp = (blockIdx.x * blockDim.x + threadIdx.x) >> 5;
    int lane = threadIdx.x & 31;
    if (warp >= N_NODES) return;

    int start = g_rowstart[warp];
    int cnt = g_count[warp];
    const float4* xf = (const float4*)feat;

    float4 acc = make_float4(0.f, 0.f, 0.f, 0.f);
    float eacc = 0.f;
    bool do_ea = WITH_EA && (lane < 16);

    int s = 0, e = 0;
    if (cnt > 0) {
        s = g_src[start];
        if (WITH_EA) e = g_perm[start];
    }
    for (int i = 0; i < cnt; i++) {
        int s2 = 0, e2 = 0;
        if (i + 1 < cnt) {
            s2 = g_src[start + i + 1];
            if (WITH_EA) e2 = g_perm[start + i + 1];
        }
        float4 v = xf[(size_t)s * 32 + lane];
        acc.x += v.x; acc.y += v.y; acc.z += v.z; acc.w += v.w;
        if (do_ea) eacc += ea[(size_t)e * EDGE_IN + lane];
        s = s2; e = e2;
    }

    ((float4*)(g_A + (size_t)warp * KDIM))[lane] = acc;
    if (do_ea) g_A[(size_t)warp * KDIM + NODE_IN + lane] = eacc;
}

// ================= tensor-core GEMM via mma.sync (sm_80+ path) ================
// C[M,128] = A[M,144] @ W[144,128] + b, optional relu.
// bf16 3-pass split: A=Ah+Al, B=Bh+Bl; D = Ah*Bh + Ah*Bl + Al*Bh, fp32 accum.
// Whole K resident in SMEM. Padded stride 152 bf16 -> conflict-free frag loads.

#define SM_STRIDE 152                       // bf16 elements per row (padded)
#define PLANE     (128 * SM_STRIDE)         // elements per plane
#define GEMM_DYN_SMEM (4 * PLANE * 2)       // 4 planes of bf16 = 155648 B

#define MMA16816(d, a, b)                                                     \
    asm volatile(                                                             \
        "mma.sync.aligned.m16n8k16.row.col.f32.bf16.bf16.f32 "                \
        "{%0,%1,%2,%3}, {%4,%5,%6,%7}, {%8,%9}, {%0,%1,%2,%3};"               \
        : "+f"((d)[0]), "+f"((d)[1]), "+f"((d)[2]), "+f"((d)[3])              \
        : "r"((a)[0]), "r"((a)[1]), "r"((a)[2]), "r"((a)[3]),                 \
          "r"((b)[0]), "r"((b)[1]))

__device__ __forceinline__ uint32_t pack_bf16x2(__nv_bfloat16 lo, __nv_bfloat16 hi) {
    __nv_bfloat162 p = __halves2bfloat162(lo, hi);   // .x = lo addr half
    return *(uint32_t*)&p;
}

__global__ __launch_bounds__(256, 1)
void k_gemm_mma(const float* __restrict__ A,
                const float* __restrict__ W,
                const float* __restrict__ bias,
                float* __restrict__ C,
                int M, int relu) {
    extern __shared__ __align__(16) char smraw[];
    __nv_bfloat16* sAh = (__nv_bfloat16*)smraw;       // [128 m][152 k]
    __nv_bfloat16* sAl = sAh + PLANE;
    __nv_bfloat16* sBh = sAl + PLANE;                 // [128 n][152 k] (= W^T)
    __nv_bfloat16* sBl = sBh + PLANE;

    const int tid = threadIdx.x;
    const int m0 = blockIdx.x * 128;

    // ---- stage A tile: rows m0..m0+127, k 0..143, hi/lo split ----
    for (int idx = tid; idx < 128 * 72; idx += 256) {     // 72 float2 per row
        int r = idx / 72;
        int kc = (idx - r * 72) * 2;
        int gr = m0 + r;
        float2 v = make_float2(0.f, 0.f);
        if (gr < M) v = *(const float2*)(A + (size_t)gr * KDIM + kc);
        __nv_bfloat16 h0 = __float2bfloat16(v.x);
        __nv_bfloat16 h1 = __float2bfloat16(v.y);
        __nv_bfloat16 l0 = __float2bfloat16(v.x - __bfloat162float(h0));
        __nv_bfloat16 l1 = __float2bfloat16(v.y - __bfloat162float(h1));
        int o = r * SM_STRIDE + kc;
        *(uint32_t*)(sAh + o) = pack_bf16x2(h0, h1);
        *(uint32_t*)(sAl + o) = pack_bf16x2(l0, l1);
    }
    // ---- stage B tile: B^T[n][k] = W[k][n], hi/lo split ----
    for (int idx = tid; idx < KDIM * 128; idx += 256) {
        int k = idx >> 7;          // W row
        int n = idx & 127;         // W col (coalesced global read)
        float v = W[idx];
        __nv_bfloat16 h = __float2bfloat16(v);
        __nv_bfloat16 l = __float2bfloat16(v - __bfloat162float(h));
        int o = n * SM_STRIDE + k;
        sBh[o] = h;
        sBl[o] = l;
    }
    __syncthreads();

    // ---- mma mainloop ----
    const int wid = tid >> 5;
    const int lane = tid & 31;
    const int g = lane >> 2;        // group id (0..7)
    const int t = lane & 3;         // thread in group
    const int wm = (wid >> 2) * 64; // warp M offset (0/64)
    const int wn = (wid & 3) * 32;  // warp N offset (0/32/64/96)

    float acc[4][4][4];
#pragma unroll
    for (int i = 0; i < 4; i++)
#pragma unroll
        for (int j = 0; j < 4; j++)
#pragma unroll
            for (int q = 0; q < 4; q++) acc[i][j][q] = 0.f;

#pragma unroll
    for (int ks = 0; ks < 9; ks++) {
        const int kb = ks * 16;     // k base (bf16 elems)
        uint32_t ah[4][4], al[4][4], bh[4][2], bl[4][2];
#pragma unroll
        for (int i = 0; i < 4; i++) {
            int r = wm + i * 16;
            int o0 = (r + g) * SM_STRIDE + kb + 2 * t;
            int o1 = (r + g + 8) * SM_STRIDE + kb + 2 * t;
            ah[i][0] = *(const uint32_t*)(sAh + o0);
            ah[i][1] = *(const uint32_t*)(sAh + o1);
            ah[i][2] = *(const uint32_t*)(sAh + o0 + 8);
            ah[i][3] = *(const uint32_t*)(sAh + o1 + 8);
            al[i][0] = *(const uint32_t*)(sAl + o0);
            al[i][1] = *(const uint32_t*)(sAl + o1);
            al[i][2] = *(const uint32_t*)(sAl + o0 + 8);
            al[i][3] = *(const uint32_t*)(sAl + o1 + 8);
        }
#pragma unroll
        for (int j = 0; j < 4; j++) {
            int n = wn + j * 8 + g;
            int o = n * SM_STRIDE + kb + 2 * t;
            bh[j][0] = *(const uint32_t*)(sBh + o);
            bh[j][1] = *(const uint32_t*)(sBh + o + 8);
            bl[j][0] = *(const uint32_t*)(sBl + o);
            bl[j][1] = *(const uint32_t*)(sBl + o + 8);
        }
#pragma unroll
        for (int i = 0; i < 4; i++)
#pragma unroll
            for (int j = 0; j < 4; j++) {
                MMA16816(acc[i][j], ah[i], bh[j]);
                MMA16816(acc[i][j], ah[i], bl[j]);
                MMA16816(acc[i][j], al[i], bh[j]);
            }
    }

    // ---- epilogue: bias + relu, direct global stores (float2) ----
#pragma unroll
    for (int j = 0; j < 4; j++) {
        int c = wn + j * 8 + 2 * t;
        float2 bb = *(const float2*)(bias + c);
#pragma unroll
        for (int i = 0; i < 4; i++) {
            int r0 = m0 + wm + i * 16 + g;
            float v0 = acc[i][j][0] + bb.x;
            float v1 = acc[i][j][1] + bb.y;
            float v2 = acc[i][j][2] + bb.x;
            float v3 = acc[i][j][3] + bb.y;
            if (relu) {
                v0 = fmaxf(v0, 0.f); v1 = fmaxf(v1, 0.f);
                v2 = fmaxf(v2, 0.f); v3 = fmaxf(v3, 0.f);
            }
            if (r0 < M)
                *(float2*)(C + (size_t)r0 * 128 + c) = make_float2(v0, v1);
            if (r0 + 8 < M)
                *(float2*)(C + (size_t)(r0 + 8) * 128 + c) = make_float2(v2, v3);
        }
    }
}

// ---------------- launch ----------------
extern "C" void kernel_launch(void* const* d_in, const int* in_sizes, int n_in,
                              void* d_out, int out_size) {
    const float* x  = (const float*)d_in[0];
    const int*   ei = (const int*)d_in[1];
    const float* ea = (const float*)d_in[2];
    const float* W1 = (const float*)d_in[3];
    const float* b1 = (const float*)d_in[4];
    const float* W2 = (const float*)d_in[5];
    const float* b2 = (const float*)d_in[6];
    float* out = (float*)d_out;

    const int NB_SCAN = (N_NODES + 511) / 512;
    const int EB = (N_EDGES + 255) / 256;
    const int AGG_B = (N_NODES * 32 + 255) / 256;
    const int GEMM_B = (N_NODES + 127) / 128;   // 391

    void* p;
    cudaGetSymbolAddress(&p, g_A); float* s_A = (float*)p;
    cudaGetSymbolAddress(&p, g_h); float* s_h = (float*)p;

    cudaFuncSetAttribute(k_gemm_mma, cudaFuncAttributeMaxDynamicSharedMemorySize,
                         GEMM_DYN_SMEM);

    k_detect<<<1, 256>>>(ei);
    k_zero_counts<<<(N_NODES + 255) / 256, 256>>>();
    k_hist<<<EB, 256>>>(ei);
    k_scan1<<<NB_SCAN, 512>>>();
    k_scan2<<<1, 128>>>(NB_SCAN);
    k_scan3<<<NB_SCAN, 512>>>();
    k_scatter<<<EB, 256>>>(ei);

    // layer 1: aggregate x + edge_attr, then mma GEMM with relu -> g_h
    k_agg<true><<<AGG_B, 256>>>(x, ea);
    k_gemm_mma<<<GEMM_B, 256, GEMM_DYN_SMEM>>>(s_A, W1, b1, s_h, N_NODES, 1);

    // layer 2: aggregate h into cols 0..127 (edge cols 128..143 preserved)
    k_agg<false><<<AGG_B, 256>>>(s_h, nullptr);
    k_gemm_mma<<<GEMM_B, 256, GEMM_DYN_SMEM>>>(s_A, W2, b2, out, N_NODES, 0);
}